// round 1
// baseline (speedup 1.0000x reference)
#include <cuda_runtime.h>
#include <cuda_bf16.h>

#define NS   16      // n_samples
#define NP   2048    // n_points
#define DIM  64      // dims
#define KNN  16      // K
#define QT   128     // queries per block (= threads per block)
#define PT   128     // points per shared tile

__global__ __launch_bounds__(QT, 2)
void knn_graph_kernel(const float* __restrict__ h,
                      float* __restrict__ out_dist,
                      float* __restrict__ out_dst,
                      float* __restrict__ out_src)
{
    __shared__ float pts[PT][DIM];   // 32 KB point tile
    __shared__ float pnorm[PT];

    const int b   = blockIdx.x;
    const int s   = b / (NP / QT);
    const int qt  = b % (NP / QT);
    const int tid = threadIdx.x;
    const int qi  = qt * QT + tid;

    const float* hs = h + (size_t)s * NP * DIM;

    // ---- load this thread's query row into registers, compute its norm ----
    float4 q[DIM / 4];
    float  qn = 0.0f;
    {
        const float4* qp = reinterpret_cast<const float4*>(hs + (size_t)qi * DIM);
        #pragma unroll
        for (int i = 0; i < DIM / 4; i++) {
            q[i] = qp[i];
            qn += q[i].x * q[i].x + q[i].y * q[i].y
                + q[i].z * q[i].z + q[i].w * q[i].w;
        }
    }

    // ---- per-thread top-K (sorted ascending; ties keep earlier index) ----
    float best_d[KNN];
    int   best_i[KNN];
    #pragma unroll
    for (int k = 0; k < KNN; k++) { best_d[k] = 3.4e38f; best_i[k] = 0; }

    for (int jt = 0; jt < NP; jt += PT) {
        __syncthreads();
        // ---- cooperative coalesced tile load: PT*DIM floats = 2048 float4 ----
        {
            const float4* tp = reinterpret_cast<const float4*>(hs + (size_t)jt * DIM);
            float4*       sp = reinterpret_cast<float4*>(&pts[0][0]);
            #pragma unroll
            for (int i = 0; i < (PT * DIM / 4) / QT; i++)
                sp[tid + i * QT] = tp[tid + i * QT];
        }
        __syncthreads();
        // ---- point norms for the tile (thread t -> point t) ----
        {
            float pn = 0.0f;
            const float* pp = &pts[tid][0];
            #pragma unroll
            for (int i = 0; i < DIM / 4; i++) {
                float4 v = reinterpret_cast<const float4*>(pp)[i];
                pn += v.x * v.x + v.y * v.y + v.z * v.z + v.w * v.w;
            }
            pnorm[tid] = pn;
        }
        __syncthreads();

        // ---- distances to the PT tile points (broadcast LDS, 4 FMA chains) ----
        #pragma unroll 2
        for (int jj = 0; jj < PT; jj++) {
            float4 acc = make_float4(0.f, 0.f, 0.f, 0.f);
            const float4* pp = reinterpret_cast<const float4*>(&pts[jj][0]);
            #pragma unroll
            for (int i = 0; i < DIM / 4; i++) {
                float4 v = pp[i];
                acc.x = fmaf(q[i].x, v.x, acc.x);
                acc.y = fmaf(q[i].y, v.y, acc.y);
                acc.z = fmaf(q[i].z, v.z, acc.z);
                acc.w = fmaf(q[i].w, v.w, acc.w);
            }
            float dot  = (acc.x + acc.y) + (acc.z + acc.w);
            float dist = qn + pnorm[jj] - 2.0f * dot;

            // strict < on the guard: a tie with the current worst keeps the
            // earlier (already-stored) index, matching lax.top_k stability.
            if (dist < best_d[KNN - 1]) {
                float dd  = dist;
                int   idx = jt + jj;
                #pragma unroll
                for (int k = 0; k < KNN; k++) {
                    // strict <: equal-valued existing entries stay in front
                    if (dd < best_d[k]) {
                        float td = best_d[k]; int ti = best_i[k];
                        best_d[k] = dd;  best_i[k] = idx;
                        dd = td;         idx = ti;
                    }
                }
            }
        }
    }

    // ---- write: knn_dist | dst | src  (all fp32; indices are exact) ----
    const size_t base = ((size_t)s * NP + qi) * KNN;
    const float  srcv = (float)(s * NP + qi);
    const float  offs = (float)(s * NP);
    #pragma unroll
    for (int k = 0; k < KNN; k++) {
        out_dist[base + k] = best_d[k];
        out_dst [base + k] = (float)best_i[k] + offs;
        out_src [base + k] = srcv;
    }
}

extern "C" void kernel_launch(void* const* d_in, const int* in_sizes, int n_in,
                              void* d_out, int out_size)
{
    const float* h = (const float*)d_in[0];
    // d_in[1] is K (=16), compile-time constant here.

    float* out      = (float*)d_out;
    const size_t nE = (size_t)NS * NP * KNN;   // 524288
    float* out_dist = out;
    float* out_dst  = out + nE;
    float* out_src  = out + 2 * nE;

    dim3 grid(NS * (NP / QT));   // 256 blocks
    dim3 block(QT);              // 128 threads
    knn_graph_kernel<<<grid, block>>>(h, out_dist, out_dst, out_src);
}

// round 2
// speedup vs baseline: 1.1009x; 1.1009x over previous
#include <cuda_runtime.h>
#include <cuda_bf16.h>
#include <cstdint>

#define NS   16      // n_samples
#define NP   2048    // n_points
#define DIM  64      // dims
#define KNN  16      // K
#define QT   128     // queries per block (= threads per block)
#define PT   128     // points per shared tile

// ---- packed fp32x2 ops (sm_100+; exactly two scalar fp32 ops) ----
__device__ __forceinline__ uint64_t ffma2(uint64_t a, uint64_t b, uint64_t c) {
    uint64_t d;
    asm("fma.rn.f32x2 %0, %1, %2, %3;" : "=l"(d) : "l"(a), "l"(b), "l"(c));
    return d;
}
__device__ __forceinline__ uint64_t fadd2(uint64_t a, uint64_t b) {
    uint64_t d;
    asm("add.rn.f32x2 %0, %1, %2;" : "=l"(d) : "l"(a), "l"(b));
    return d;
}
__device__ __forceinline__ uint64_t pack2(float lo, float hi) {
    return (uint64_t)__float_as_uint(lo) | ((uint64_t)__float_as_uint(hi) << 32);
}

__global__ __launch_bounds__(QT, 3)
void knn_graph_kernel(const float* __restrict__ h,
                      float* __restrict__ out_dist,
                      float* __restrict__ out_dst,
                      float* __restrict__ out_src)
{
    __shared__ __align__(16) float pts[PT][DIM];   // 32 KB point tile
    __shared__ float pnorm[PT];

    const int b   = blockIdx.x;
    const int s   = b / (NP / QT);
    const int qt  = b % (NP / QT);
    const int tid = threadIdx.x;
    const int qi  = qt * QT + tid;

    const float* hs = h + (size_t)s * NP * DIM;

    // ---- query row into packed f32x2 registers + norm ----
    uint64_t qq[DIM / 2];
    float    qn = 0.0f;
    {
        const float4* qp = reinterpret_cast<const float4*>(hs + (size_t)qi * DIM);
        #pragma unroll
        for (int i = 0; i < DIM / 4; i++) {
            float4 v = qp[i];
            qn += v.x * v.x + v.y * v.y + v.z * v.z + v.w * v.w;
            qq[2 * i]     = pack2(v.x, v.y);
            qq[2 * i + 1] = pack2(v.z, v.w);
        }
    }

    // ---- per-thread top-K (sorted ascending; ties keep earlier index) ----
    float best_d[KNN];
    int   best_i[KNN];
    #pragma unroll
    for (int k = 0; k < KNN; k++) { best_d[k] = 3.4e38f; best_i[k] = 0; }

    for (int jt = 0; jt < NP; jt += PT) {
        __syncthreads();
        // ---- cooperative coalesced tile load ----
        {
            const float4* tp = reinterpret_cast<const float4*>(hs + (size_t)jt * DIM);
            float4*       sp = reinterpret_cast<float4*>(&pts[0][0]);
            #pragma unroll
            for (int i = 0; i < (PT * DIM / 4) / QT; i++)
                sp[tid + i * QT] = tp[tid + i * QT];
        }
        __syncthreads();
        // ---- point norms (thread t -> point t) ----
        {
            float pn = 0.0f;
            #pragma unroll
            for (int i = 0; i < DIM / 4; i++) {
                float4 v = reinterpret_cast<const float4*>(&pts[tid][0])[i];
                pn += v.x * v.x + v.y * v.y + v.z * v.z + v.w * v.w;
            }
            pnorm[tid] = pn;
        }
        __syncthreads();

        // ---- distances: 16 LDS.128 + 32 FFMA2 per point ----
        #pragma unroll 2
        for (int jj = 0; jj < PT; jj++) {
            const ulonglong2* pp = reinterpret_cast<const ulonglong2*>(&pts[jj][0]);
            uint64_t a0 = 0, a1 = 0, a2 = 0, a3 = 0;   // {+0,+0} packed
            #pragma unroll
            for (int i = 0; i < DIM / 4; i += 2) {     // 16 x LDS.128
                ulonglong2 v0 = pp[i];
                ulonglong2 v1 = pp[i + 1];
                a0 = ffma2(qq[2 * i],     v0.x, a0);
                a1 = ffma2(qq[2 * i + 1], v0.y, a1);
                a2 = ffma2(qq[2 * i + 2], v1.x, a2);
                a3 = ffma2(qq[2 * i + 3], v1.y, a3);
            }
            uint64_t sred = fadd2(fadd2(a0, a1), fadd2(a2, a3));
            float lo  = __uint_as_float((uint32_t)sred);
            float hi  = __uint_as_float((uint32_t)(sred >> 32));
            float dot = lo + hi;
            float dist = fmaf(-2.0f, dot, qn + pnorm[jj]);

            // strict <: tie with current worst keeps earlier index (lax.top_k order)
            if (dist < best_d[KNN - 1]) {
                float dd  = dist;
                int   idx = jt + jj;
                #pragma unroll
                for (int k = 0; k < KNN; k++) {
                    if (dd < best_d[k]) {
                        float td = best_d[k]; int ti = best_i[k];
                        best_d[k] = dd;  best_i[k] = idx;
                        dd = td;         idx = ti;
                    }
                }
            }
        }
    }

    // ---- write: knn_dist | dst | src  (fp32; indices exact in fp32) ----
    const size_t base = ((size_t)s * NP + qi) * KNN;
    const float  srcv = (float)(s * NP + qi);
    const float  offs = (float)(s * NP);
    #pragma unroll
    for (int k = 0; k < KNN; k++) {
        out_dist[base + k] = best_d[k];
        out_dst [base + k] = (float)best_i[k] + offs;
        out_src [base + k] = srcv;
    }
}

extern "C" void kernel_launch(void* const* d_in, const int* in_sizes, int n_in,
                              void* d_out, int out_size)
{
    const float* h = (const float*)d_in[0];

    float* out      = (float*)d_out;
    const size_t nE = (size_t)NS * NP * KNN;   // 524288
    float* out_dist = out;
    float* out_dst  = out + nE;
    float* out_src  = out + 2 * nE;

    dim3 grid(NS * (NP / QT));   // 256 blocks
    dim3 block(QT);              // 128 threads
    knn_graph_kernel<<<grid, block>>>(h, out_dist, out_dst, out_src);
}